// round 4
// baseline (speedup 1.0000x reference)
#include <cuda_runtime.h>

#define DIM 1024
#define NHEADS 16
#define HD 64
#define BATCH 2
#define SEQ 2048
#define ROWS (BATCH*SEQ)   // 4096

// ---------------- scratch (device globals; no allocation allowed) ----------
__device__ __align__(16) float g_q[ROWS * DIM];
__device__ __align__(16) float g_k[ROWS * DIM];
__device__ __align__(16) float g_v[ROWS * DIM];
__device__ __align__(16) float g_ctx[ROWS * DIM];

// ===========================================================================
// GEMM: C[M,N] = A[M,K] @ W[K,N] + bias[N]
// M=4096, N=K=1024. Block tile 128x128, k-tile 8, 256 threads, 8x8 micro-tile
// (split as 2x(4) rows x 2x(4) cols for conflict-free float4 smem reads).
// ===========================================================================
#define GM ROWS
#define GN DIM
#define GK DIM

__global__ __launch_bounds__(256) void gemm_bias(
    const float* __restrict__ A, const float* __restrict__ W,
    const float* __restrict__ bias, float* __restrict__ C)
{
    __shared__ float As[8][132];   // A transposed: As[k][m], 132 = 4*33 (16B-aligned rows)
    __shared__ float Bs[8][132];   // Bs[k][n]

    const int tid = threadIdx.x;
    const int tx  = tid & 15;      // 0..15  -> N micro
    const int ty  = tid >> 4;      // 0..15  -> M micro
    const int m0  = blockIdx.y * 128;
    const int n0  = blockIdx.x * 128;

    float acc[8][8];
    #pragma unroll
    for (int i = 0; i < 8; i++)
        #pragma unroll
        for (int j = 0; j < 8; j++) acc[i][j] = 0.f;

    const int ar  = tid >> 1;         // 0..127 : A row within tile
    const int akq = (tid & 1) * 4;    // 0 or 4 : A k offset
    const int bk  = tid >> 5;         // 0..7   : B k row
    const int bc  = (tid & 31) * 4;   // 0..124 : B col offset

    for (int k0 = 0; k0 < GK; k0 += 8) {
        float4 av = *(const float4*)(A + (size_t)(m0 + ar) * GK + k0 + akq);
        float4 bv = *(const float4*)(W + (size_t)(k0 + bk) * GN + n0 + bc);
        As[akq + 0][ar] = av.x;
        As[akq + 1][ar] = av.y;
        As[akq + 2][ar] = av.z;
        As[akq + 3][ar] = av.w;
        *(float4*)&Bs[bk][bc] = bv;
        __syncthreads();

        #pragma unroll
        for (int kk = 0; kk < 8; kk++) {
            float4 a0 = *(float4*)&As[kk][ty * 4];
            float4 a1 = *(float4*)&As[kk][64 + ty * 4];
            float4 b0 = *(float4*)&Bs[kk][tx * 4];
            float4 b1 = *(float4*)&Bs[kk][64 + tx * 4];
            float a[8] = {a0.x, a0.y, a0.z, a0.w, a1.x, a1.y, a1.z, a1.w};
            float b[8] = {b0.x, b0.y, b0.z, b0.w, b1.x, b1.y, b1.z, b1.w};
            #pragma unroll
            for (int i = 0; i < 8; i++)
                #pragma unroll
                for (int j = 0; j < 8; j++)
                    acc[i][j] += a[i] * b[j];
        }
        __syncthreads();
    }

    // epilogue: add bias, write float4s
    #pragma unroll
    for (int i = 0; i < 8; i++) {
        const int m = m0 + ((i < 4) ? (ty * 4 + i) : (64 + ty * 4 + (i - 4)));
        #pragma unroll
        for (int jh = 0; jh < 2; jh++) {
            const int n = n0 + jh * 64 + tx * 4;
            float4 bv = *(const float4*)(bias + n);
            float4 o;
            o.x = acc[i][jh * 4 + 0] + bv.x;
            o.y = acc[i][jh * 4 + 1] + bv.y;
            o.z = acc[i][jh * 4 + 2] + bv.z;
            o.w = acc[i][jh * 4 + 3] + bv.w;
            *(float4*)(C + (size_t)m * GN + n) = o;
        }
    }
}

// ===========================================================================
// Flash-style attention.
// Per CTA: one (batch b, head h, 64-row q-tile). Loops over 32 s-tiles of 64.
// 256 threads: thread (ty,tx): ty -> 4 q rows (ty*4+i), tx -> 4 s cols / 4 hd cols.
// Smem (dynamic, 69632B): Qt[d][q], Kt[d][s], Vs[s][d], Ps[q][s], stride 68.
// ===========================================================================
#define SSTR 68   // smem row stride (floats): mult of 4 (16B align), odd/32 banking

__global__ __launch_bounds__(256) void attn_kernel(
    const float* __restrict__ Q, const float* __restrict__ K,
    const float* __restrict__ V, float* __restrict__ O)
{
    extern __shared__ float smem[];
    float* Qt = smem;                 // [64 d][64 q]
    float* Kt = Qt + 64 * SSTR;       // [64 d][64 s]
    float* Vs = Kt + 64 * SSTR;       // [64 s][64 d]
    float* Ps = Vs + 64 * SSTR;       // [64 q][64 s]

    const int tid = threadIdx.x;
    const int tx  = tid & 15;
    const int ty  = tid >> 4;
    const int qt  = blockIdx.x;       // 0..31
    const int h   = blockIdx.y;       // 0..15
    const int b   = blockIdx.z;       // 0..1

    const float scale = 0.125f;       // 1/sqrt(64)
    const size_t base = ((size_t)b * SEQ) * DIM + (size_t)h * HD;

    // ---- load Q tile, transposed & pre-scaled: Qt[d][q] ----
    #pragma unroll
    for (int u = 0; u < 4; u++) {
        const int idx4 = tid + u * 256;       // 0..1023
        const int q    = idx4 >> 4;           // 0..63
        const int d4   = idx4 & 15;           // 0..15
        float4 v = *(const float4*)(Q + base + (size_t)(qt * 64 + q) * DIM + d4 * 4);
        Qt[(d4 * 4 + 0) * SSTR + q] = v.x * scale;
        Qt[(d4 * 4 + 1) * SSTR + q] = v.y * scale;
        Qt[(d4 * 4 + 2) * SSTR + q] = v.z * scale;
        Qt[(d4 * 4 + 3) * SSTR + q] = v.w * scale;
    }

    float m[4], l[4], o[4][4];
    #pragma unroll
    for (int i = 0; i < 4; i++) {
        m[i] = -1e30f; l[i] = 0.f;
        #pragma unroll
        for (int j = 0; j < 4; j++) o[i][j] = 0.f;
    }

    for (int st = 0; st < SEQ / 64; st++) {
        __syncthreads();   // prev iteration's smem reads done

        // ---- load K tile (transposed) and V tile ----
        #pragma unroll
        for (int u = 0; u < 4; u++) {
            const int idx4 = tid + u * 256;
            const int s    = idx4 >> 4;
            const int d4   = idx4 & 15;
            const size_t g = base + (size_t)(st * 64 + s) * DIM + d4 * 4;
            float4 kv = *(const float4*)(K + g);
            Kt[(d4 * 4 + 0) * SSTR + s] = kv.x;
            Kt[(d4 * 4 + 1) * SSTR + s] = kv.y;
            Kt[(d4 * 4 + 2) * SSTR + s] = kv.z;
            Kt[(d4 * 4 + 3) * SSTR + s] = kv.w;
            *(float4*)&Vs[s * SSTR + d4 * 4] = *(const float4*)(V + g);
        }
        __syncthreads();

        // ---- S = Q K^T (4x4 per thread) ----
        float S[4][4];
        #pragma unroll
        for (int i = 0; i < 4; i++)
            #pragma unroll
            for (int j = 0; j < 4; j++) S[i][j] = 0.f;

        #pragma unroll 8
        for (int d = 0; d < 64; d++) {
            float4 qv = *(float4*)&Qt[d * SSTR + ty * 4];
            float4 kv = *(float4*)&Kt[d * SSTR + tx * 4];
            float qa[4] = {qv.x, qv.y, qv.z, qv.w};
            float ka[4] = {kv.x, kv.y, kv.z, kv.w};
            #pragma unroll
            for (int i = 0; i < 4; i++)
                #pragma unroll
                for (int j = 0; j < 4; j++)
                    S[i][j] += qa[i] * ka[j];
        }

        // ---- online softmax update ----
        #pragma unroll
        for (int i = 0; i < 4; i++) {
            float mloc = fmaxf(fmaxf(S[i][0], S[i][1]), fmaxf(S[i][2], S[i][3]));
            #pragma unroll
            for (int off = 8; off >= 1; off >>= 1)
                mloc = fmaxf(mloc, __shfl_xor_sync(0xffffffffu, mloc, off));
            const float mnew = fmaxf(m[i], mloc);
            const float corr = __expf(m[i] - mnew);
            float4 p;
            p.x = __expf(S[i][0] - mnew);
            p.y = __expf(S[i][1] - mnew);
            p.z = __expf(S[i][2] - mnew);
            p.w = __expf(S[i][3] - mnew);
            float rs = p.x + p.y + p.z + p.w;
            #pragma unroll
            for (int off = 8; off >= 1; off >>= 1)
                rs += __shfl_xor_sync(0xffffffffu, rs, off);
            l[i] = l[i] * corr + rs;
            m[i] = mnew;
            #pragma unroll
            for (int j = 0; j < 4; j++) o[i][j] *= corr;
            *(float4*)&Ps[(ty * 4 + i) * SSTR + tx * 4] = p;
        }
        __syncthreads();

        // ---- O += P @ V (s unrolled by 4, float4 smem reads) ----
        #pragma unroll 4
        for (int s0 = 0; s0 < 64; s0 += 4) {
            float4 pr[4];
            #pragma unroll
            for (int i = 0; i < 4; i++)
                pr[i] = *(float4*)&Ps[(ty * 4 + i) * SSTR + s0];
            #pragma unroll
            for (int u = 0; u < 4; u++) {
                float4 vv = *(float4*)&Vs[(s0 + u) * SSTR + tx * 4];
                #pragma unroll
                for (int i = 0; i < 4; i++) {
                    const float pp = (u == 0) ? pr[i].x :
                                     (u == 1) ? pr[i].y :
                                     (u == 2) ? pr[i].z : pr[i].w;
                    o[i][0] += pp * vv.x;
                    o[i][1] += pp * vv.y;
                    o[i][2] += pp * vv.z;
                    o[i][3] += pp * vv.w;
                }
            }
        }
    }

    // ---- finalize: divide by l, write ctx ----
    #pragma unroll
    for (int i = 0; i < 4; i++) {
        const float inv = 1.f / l[i];
        const int t = qt * 64 + ty * 4 + i;
        float4 ov;
        ov.x = o[i][0] * inv;
        ov.y = o[i][1] * inv;
        ov.z = o[i][2] * inv;
        ov.w = o[i][3] * inv;
        *(float4*)(O + base + (size_t)t * DIM + tx * 4) = ov;
    }
}

// ===========================================================================
// launch
// ===========================================================================
extern "C" void kernel_launch(void* const* d_in, const int* in_sizes, int n_in,
                              void* d_out, int out_size)
{
    const float* x  = (const float*)d_in[0];
    const float* Wq = (const float*)d_in[1];
    const float* bq = (const float*)d_in[2];
    const float* Wk = (const float*)d_in[3];
    const float* bk = (const float*)d_in[4];
    const float* Wv = (const float*)d_in[5];
    const float* bv = (const float*)d_in[6];
    const float* Wo = (const float*)d_in[7];
    const float* bo = (const float*)d_in[8];
    float* out = (float*)d_out;

    float *qp, *kp, *vp, *cp;
    cudaGetSymbolAddress((void**)&qp, g_q);
    cudaGetSymbolAddress((void**)&kp, g_k);
    cudaGetSymbolAddress((void**)&vp, g_v);
    cudaGetSymbolAddress((void**)&cp, g_ctx);

    const dim3 ggrid(GN / 128, GM / 128);   // (8, 32)

    gemm_bias<<<ggrid, 256>>>(x, Wq, bq, qp);
    gemm_bias<<<ggrid, 256>>>(x, Wk, bk, kp);
    gemm_bias<<<ggrid, 256>>>(x, Wv, bv, vp);

    const int smem_bytes = 4 * 64 * SSTR * (int)sizeof(float);   // 69632
    cudaFuncSetAttribute(attn_kernel, cudaFuncAttributeMaxDynamicSharedMemorySize,
                         smem_bytes);
    attn_kernel<<<dim3(SEQ / 64, NHEADS, BATCH), 256, smem_bytes>>>(qp, kp, vp, cp);

    gemm_bias<<<ggrid, 256>>>(cp, Wo, bo, out);
}

// round 7
// speedup vs baseline: 2.1789x; 2.1789x over previous
#include <cuda_runtime.h>
#include <cuda_bf16.h>
#include <cstdint>

#define DIM 1024
#define NHEADS 16
#define HD 64
#define BATCH 2
#define SEQ 2048
#define ROWS (BATCH*SEQ)   // 4096
#define KP (3*DIM)         // 3072: split-bf16 extended K

// ---------------- scratch (device globals; no allocation allowed) ----------
__device__ __align__(16) float g_q[ROWS * DIM];
__device__ __align__(16) float g_k[ROWS * DIM];
__device__ __align__(16) float g_v[ROWS * DIM];
__device__ __align__(16) float g_ctx[ROWS * DIM];

// packed split-bf16 operands: A' = [Ahi | Ahi | Alo]  (row-major, K'=3072)
//                             B' = [Bhi ; Blo ; Bhi]  stored transposed [N][K']
__device__ __align__(16) __nv_bfloat16 g_apack[ROWS * KP];
__device__ __align__(16) __nv_bfloat16 g_bpack[4][DIM * KP];

// ===========================================================================
// PTX helpers (legacy tensor-core path: valid at plain compute_103)
// ===========================================================================
__device__ __forceinline__ uint32_t smem_u32(const void* p) {
    uint32_t a;
    asm("{ .reg .u64 t; cvta.to.shared.u64 t, %1; cvt.u32.u64 %0, t; }"
        : "=r"(a) : "l"(p));
    return a;
}

#define CP_ASYNC16(dst, src) \
    asm volatile("cp.async.cg.shared.global [%0], [%1], 16;" \
                 :: "r"(dst), "l"(src) : "memory")
#define CP_COMMIT() asm volatile("cp.async.commit_group;" ::: "memory")
#define CP_WAIT2()  asm volatile("cp.async.wait_group 2;"  ::: "memory")

#define LDSM_X4(r, addr) \
    asm volatile("ldmatrix.sync.aligned.m8n8.x4.shared.b16 {%0,%1,%2,%3}, [%4];" \
        : "=r"((r)[0]), "=r"((r)[1]), "=r"((r)[2]), "=r"((r)[3]) : "r"(addr))

#define MMA16816(d, a, b0, b1) \
    asm volatile("mma.sync.aligned.m16n8k16.row.col.f32.bf16.bf16.f32 " \
        "{%0,%1,%2,%3}, {%4,%5,%6,%7}, {%8,%9}, {%0,%1,%2,%3};" \
        : "+f"((d)[0]), "+f"((d)[1]), "+f"((d)[2]), "+f"((d)[3]) \
        : "r"((a)[0]), "r"((a)[1]), "r"((a)[2]), "r"((a)[3]), "r"(b0), "r"(b1))

// ===========================================================================
// conversion kernels
// ===========================================================================
// A (fp32 [4096,1024]) -> A' bf16 [4096, 3072] = [hi | hi | lo]
__global__ __launch_bounds__(256) void conv_a(
    const float* __restrict__ A, __nv_bfloat16* __restrict__ P)
{
    const int row = blockIdx.x;
    const int c4  = threadIdx.x * 4;
    float4 v = *(const float4*)(A + (size_t)row * DIM + c4);
    float xs[4] = {v.x, v.y, v.z, v.w};
    __align__(8) __nv_bfloat16 h[4], L[4];
    #pragma unroll
    for (int j = 0; j < 4; j++) {
        __nv_bfloat16 hh = __float2bfloat16(xs[j]);
        h[j] = hh;
        L[j] = __float2bfloat16(xs[j] - __bfloat162float(hh));
    }
    __nv_bfloat16* rp = P + (size_t)row * KP;
    *(uint2*)(rp + c4)            = *(const uint2*)h;
    *(uint2*)(rp + DIM + c4)      = *(const uint2*)h;
    *(uint2*)(rp + 2 * DIM + c4)  = *(const uint2*)L;
}

// W (fp32 [K=1024, N=1024]) -> B' bf16 [N=1024, K'=3072] = [hi ; lo ; hi] along K'
__global__ __launch_bounds__(256) void conv_w(
    const float* __restrict__ W, __nv_bfloat16* __restrict__ P)
{
    __shared__ float ws[32][33];
    const int k0 = blockIdx.x * 32;
    const int n0 = blockIdx.y * 32;
    const int t  = threadIdx.x;

    {   // read [32 k][32 n] tile
        const int kr = t >> 3;
        const int c4 = (t & 7) * 4;
        float4 v = *(const float4*)(W + (size_t)(k0 + kr) * DIM + n0 + c4);
        ws[kr][c4 + 0] = v.x; ws[kr][c4 + 1] = v.y;
        ws[kr][c4 + 2] = v.z; ws[kr][c4 + 3] = v.w;
    }
    __syncthreads();

    const int nr = t >> 3;
    const int k4 = (t & 7) * 4;
    __align__(8) __nv_bfloat16 h[4], L[4];
    #pragma unroll
    for (int j = 0; j < 4; j++) {
        const float x = ws[k4 + j][nr];
        __nv_bfloat16 hh = __float2bfloat16(x);
        h[j] = hh;
        L[j] = __float2bfloat16(x - __bfloat162float(hh));
    }
    __nv_bfloat16* rp = P + (size_t)(n0 + nr) * KP;
    *(uint2*)(rp + k0 + k4)            = *(const uint2*)h;
    *(uint2*)(rp + DIM + k0 + k4)      = *(const uint2*)L;
    *(uint2*)(rp + 2 * DIM + k0 + k4)  = *(const uint2*)h;
}

// ===========================================================================
// HMMA GEMM: C[4096,1024] = A'[4096,K'] @ B'^T[N,K'] + bias
// CTA 128x128, 8 warps (4m x 2n), warp tile 32x64, K-chunk 32,
// 4-stage cp.async pipeline. smem row stride 80B (conflict-free ldmatrix).
// ===========================================================================
#define NCHUNK (KP / 32)       // 96
#define SROW 80                // bytes per k-row of 32 bf16 (padded)
#define TILE_SB (128 * SROW)   // 10240
#define STAGE_SB (2 * TILE_SB) // 20480
#define GSTAGES 4

__global__ __launch_bounds__(256) void gemm_mma(
    const __nv_bfloat16* __restrict__ Ap, const __nv_bfloat16* __restrict__ Bp,
    const float* __restrict__ bias, float* __restrict__ C)
{
    extern __shared__ __align__(128) char smem[];
    const uint32_t sb = smem_u32(smem);

    const int tid  = threadIdx.x;
    const int lane = tid & 31;
    const int wid  = tid >> 5;
    const int wm   = (wid >> 1) * 32;    // warp m offset in tile
    const int wn   = (wid & 1) * 64;     // warp n offset in tile
    const int nt   = blockIdx.x;         // 0..7
    const int mt   = blockIdx.y;         // 0..31

    const char* ag = (const char*)(Ap + (size_t)(mt * 128) * KP);
    const char* bg = (const char*)(Bp + (size_t)(nt * 128) * KP);

    // per-thread load slice: 4 x 16B chunks (2 A rows' worth + 2 B)
    // id = tid + u*256; id<512 -> A(row=id>>2, c=id&3), else B
    auto issue = [&](int kc, int slot) {
        const uint32_t st = sb + slot * STAGE_SB;
        #pragma unroll
        for (int u = 0; u < 4; u++) {
            const int id = tid + u * 256;
            const int isB = id >> 9;
            const int r  = (id >> 2) & 127;
            const int c  = id & 3;
            const uint32_t dst = st + isB * TILE_SB + r * SROW + c * 16;
            const char* src = (isB ? bg : ag) + (size_t)r * (KP * 2) + kc * 64 + c * 16;
            CP_ASYNC16(dst, src);
        }
        CP_COMMIT();
    };

    float acc[2][8][4];
    #pragma unroll
    for (int mi = 0; mi < 2; mi++)
        #pragma unroll
        for (int nj = 0; nj < 8; nj++)
            #pragma unroll
            for (int r = 0; r < 4; r++) acc[mi][nj][r] = 0.f;

    // lane-derived smem addresses (invariant parts)
    const uint32_t a_row = wm + (lane & 15);
    const uint32_t a_cc  = (lane >> 4) * 16;
    const uint32_t b_row = wn + ((lane >> 4) << 3) + (lane & 7);
    const uint32_t b_cc  = ((lane >> 3) & 1) * 16;

    // prologue: stages 0..2
    issue(0, 0); issue(1, 1); issue(2, 2);

    for (int kc = 0; kc < NCHUNK; kc++) {
        const int slot = kc & 3;
        CP_WAIT2();
        __syncthreads();
        if (kc + 3 < NCHUNK) issue(kc + 3, (kc + 3) & 3);
        else CP_COMMIT();   // keep group accounting uniform

        const uint32_t As = sb + slot * STAGE_SB;
        const uint32_t Bs = As + TILE_SB;

        #pragma unroll
        for (int ki = 0; ki < 2; ki++) {
            uint32_t a[2][4], b[4][4];
            #pragma unroll
            for (int mi = 0; mi < 2; mi++)
                LDSM_X4(a[mi], As + (a_row + mi * 16) * SROW + ki * 32 + a_cc);
            #pragma unroll
            for (int ni = 0; ni < 4; ni++)
                LDSM_X4(b[ni], Bs + (b_row + ni * 16) * SROW + ki * 32 + b_cc);
            #pragma unroll
            for (int mi = 0; mi < 2; mi++)
                #pragma unroll
                for (int nj = 0; nj < 8; nj++)
                    MMA16816(acc[mi][nj], a[mi],
                             b[nj >> 1][(nj & 1) * 2], b[nj >> 1][(nj & 1) * 2 + 1]);
        }
    }

    // epilogue: D rows = mt*128 + wm + mi*16 + g (+8), cols = nt*128 + wn + nj*8 + tig*2
    const int g   = lane >> 2;
    const int tig = lane & 3;
    #pragma unroll
    for (int nj = 0; nj < 8; nj++) {
        const int col = nt * 128 + wn + nj * 8 + tig * 2;
        const float2 bv = *(const float2*)(bias + col);
        #pragma unroll
        for (int mi = 0; mi < 2; mi++) {
            const int m0 = mt * 128 + wm + mi * 16 + g;
            float2 d0 = {acc[mi][nj][0] + bv.x, acc[mi][nj][1] + bv.y};
            float2 d1 = {acc[mi][nj][2] + bv.x, acc[mi][nj][3] + bv.y};
            *(float2*)(C + (size_t)m0 * DIM + col)       = d0;
            *(float2*)(C + (size_t)(m0 + 8) * DIM + col) = d1;
        }
    }
}

// ===========================================================================
// Flash-style attention (unchanged, known-good).
// ===========================================================================
#define SSTR 68

__global__ __launch_bounds__(256) void attn_kernel(
    const float* __restrict__ Q, const float* __restrict__ K,
    const float* __restrict__ V, float* __restrict__ O)
{
    extern __shared__ float smemf[];
    float* Qt = smemf;
    float* Kt = Qt + 64 * SSTR;
    float* Vs = Kt + 64 * SSTR;
    float* Ps = Vs + 64 * SSTR;

    const int tid = threadIdx.x;
    const int tx  = tid & 15;
    const int ty  = tid >> 4;
    const int qt  = blockIdx.x;
    const int h   = blockIdx.y;
    const int b   = blockIdx.z;

    const float scale = 0.125f;
    const size_t base = ((size_t)b * SEQ) * DIM + (size_t)h * HD;

    #pragma unroll
    for (int u = 0; u < 4; u++) {
        const int idx4 = tid + u * 256;
        const int q    = idx4 >> 4;
        const int d4   = idx4 & 15;
        float4 v = *(const float4*)(Q + base + (size_t)(qt * 64 + q) * DIM + d4 * 4);
        Qt[(d4 * 4 + 0) * SSTR + q] = v.x * scale;
        Qt[(d4 * 4 + 1) * SSTR + q] = v.y * scale;
        Qt[(d4 * 4 + 2) * SSTR + q] = v.z * scale;
        Qt[(d4 * 4 + 3) * SSTR + q] = v.w * scale;
    }

    float m[4], l[4], o[4][4];
    #pragma unroll
    for (int i = 0; i < 4; i++) {
        m[i] = -1e30f; l[i] = 0.f;
        #pragma unroll
        for (int j = 0; j < 4; j++) o[i][j] = 0.f;
    }

    for (int st = 0; st < SEQ / 64; st++) {
        __syncthreads();

        #pragma unroll
        for (int u = 0; u < 4; u++) {
            const int idx4 = tid + u * 256;
            const int s    = idx4 >> 4;
            const int d4   = idx4 & 15;
            const size_t gg = base + (size_t)(st * 64 + s) * DIM + d4 * 4;
            float4 kv = *(const float4*)(K + gg);
            Kt[(d4 * 4 + 0) * SSTR + s] = kv.x;
            Kt[(d4 * 4 + 1) * SSTR + s] = kv.y;
            Kt[(d4 * 4 + 2) * SSTR + s] = kv.z;
            Kt[(d4 * 4 + 3) * SSTR + s] = kv.w;
            *(float4*)&Vs[s * SSTR + d4 * 4] = *(const float4*)(V + gg);
        }
        __syncthreads();

        float S[4][4];
        #pragma unroll
        for (int i = 0; i < 4; i++)
            #pragma unroll
            for (int j = 0; j < 4; j++) S[i][j] = 0.f;

        #pragma unroll 8
        for (int d = 0; d < 64; d++) {
            float4 qv = *(float4*)&Qt[d * SSTR + ty * 4];
            float4 kv = *(float4*)&Kt[d * SSTR + tx * 4];
            float qa[4] = {qv.x, qv.y, qv.z, qv.w};
            float ka[4] = {kv.x, kv.y, kv.z, kv.w};
            #pragma unroll
            for (int i = 0; i < 4; i++)
                #pragma unroll
                for (int j = 0; j < 4; j++)
                    S[i][j] += qa[i] * ka[j];
        }

        #pragma unroll
        for (int i = 0; i < 4; i++) {
            float mloc = fmaxf(fmaxf(S[i][0], S[i][1]), fmaxf(S[i][2], S[i][3]));
            #pragma unroll
            for (int off = 8; off >= 1; off >>= 1)
                mloc = fmaxf(mloc, __shfl_xor_sync(0xffffffffu, mloc, off));
            const float mnew = fmaxf(m[i], mloc);
            const float corr = __expf(m[i] - mnew);
            float4 p;
            p.x = __expf(S[i][0] - mnew);
            p.y = __expf(S[i][1] - mnew);
            p.z = __expf(S[i][2] - mnew);
            p.w = __expf(S[i][3] - mnew);
            float rs = p.x + p.y + p.z + p.w;
            #pragma unroll
            for (int off = 8; off >= 1; off >>= 1)
                rs += __shfl_xor_sync(0xffffffffu, rs, off);
            l[i] = l[i] * corr + rs;
            m[i] = mnew;
            #pragma unroll
            for (int j = 0; j < 4; j++) o[i][j] *= corr;
            *(float4*)&Ps[(ty * 4 + i) * SSTR + tx * 4] = p;
        }
        __syncthreads();

        #pragma unroll 4
        for (int s0 = 0; s0 < 64; s0 += 4) {
            float4 pr[4];
            #pragma unroll
            for (int i = 0; i < 4; i++)
                pr[i] = *(float4*)&Ps[(ty * 4 + i) * SSTR + s0];
            #pragma unroll
            for (int u = 0; u < 4; u++) {
                float4 vv = *(float4*)&Vs[(s0 + u) * SSTR + tx * 4];
                #pragma unroll
                for (int i = 0; i < 4; i++) {
                    const float pp = (u == 0) ? pr[i].x :
                                     (u == 1) ? pr[i].y :
                                     (u == 2) ? pr[i].z : pr[i].w;
                    o[i][0] += pp * vv.x;
                    o[i][1] += pp * vv.y;
                    o[i][2] += pp * vv.z;
                    o[i][3] += pp * vv.w;
                }
            }
        }
    }

    #pragma unroll
    for (int i = 0; i < 4; i++) {
        const float inv = 1.f / l[i];
        const int t = qt * 64 + ty * 4 + i;
        float4 ov;
        ov.x = o[i][0] * inv;
        ov.y = o[i][1] * inv;
        ov.z = o[i][2] * inv;
        ov.w = o[i][3] * inv;
        *(float4*)(O + base + (size_t)t * DIM + tx * 4) = ov;
    }
}

// ===========================================================================
// launch
// ===========================================================================
extern "C" void kernel_launch(void* const* d_in, const int* in_sizes, int n_in,
                              void* d_out, int out_size)
{
    const float* x  = (const float*)d_in[0];
    const float* Wq = (const float*)d_in[1];
    const float* bq = (const float*)d_in[2];
    const float* Wk = (const float*)d_in[3];
    const float* bk = (const float*)d_in[4];
    const float* Wv = (const float*)d_in[5];
    const float* bv = (const float*)d_in[6];
    const float* Wo = (const float*)d_in[7];
    const float* bo = (const float*)d_in[8];
    float* out = (float*)d_out;

    float *qp, *kp, *vp, *cp;
    cudaGetSymbolAddress((void**)&qp, g_q);
    cudaGetSymbolAddress((void**)&kp, g_k);
    cudaGetSymbolAddress((void**)&vp, g_v);
    cudaGetSymbolAddress((void**)&cp, g_ctx);
    __nv_bfloat16 *ap, *bp;
    cudaGetSymbolAddress((void**)&ap, g_apack);
    cudaGetSymbolAddress((void**)&bp, g_bpack);

    const int gsmem = GSTAGES * STAGE_SB;   // 81920
    cudaFuncSetAttribute(gemm_mma, cudaFuncAttributeMaxDynamicSharedMemorySize, gsmem);

    const dim3 gconv_w(32, 32);
    const dim3 ggemm(8, 32);
    const size_t bstride = (size_t)DIM * KP;

    // weight conversions
    conv_w<<<gconv_w, 256>>>(Wq, bp + 0 * bstride);
    conv_w<<<gconv_w, 256>>>(Wk, bp + 1 * bstride);
    conv_w<<<gconv_w, 256>>>(Wv, bp + 2 * bstride);
    conv_w<<<gconv_w, 256>>>(Wo, bp + 3 * bstride);

    // x split-pack
    conv_a<<<ROWS, 256>>>(x, ap);

    // Q/K/V projections on tensor cores (HMMA)
    gemm_mma<<<ggemm, 256, gsmem>>>(ap, bp + 0 * bstride, bq, qp);
    gemm_mma<<<ggemm, 256, gsmem>>>(ap, bp + 1 * bstride, bk, kp);
    gemm_mma<<<ggemm, 256, gsmem>>>(ap, bp + 2 * bstride, bv, vp);

    // attention (SIMT flash, fp32)
    const int asmem = 4 * 64 * SSTR * (int)sizeof(float);
    cudaFuncSetAttribute(attn_kernel, cudaFuncAttributeMaxDynamicSharedMemorySize, asmem);
    attn_kernel<<<dim3(SEQ / 64, NHEADS, BATCH), 256, asmem>>>(qp, kp, vp, cp);

    // output projection
    conv_a<<<ROWS, 256>>>(cp, ap);
    gemm_mma<<<ggemm, 256, gsmem>>>(ap, bp + 3 * bstride, bo, out);
}

// round 8
// speedup vs baseline: 4.7813x; 2.1944x over previous
#include <cuda_runtime.h>
#include <cuda_bf16.h>
#include <cuda_fp16.h>
#include <cstdint>

#define DIM 1024
#define NHEADS 16
#define HD 64
#define BATCH 2
#define SEQ 2048
#define ROWS (BATCH*SEQ)   // 4096
#define KP (3*DIM)         // 3072: split-bf16 extended K

// Q pre-scale: 1/sqrt(64) * log2(e)  (softmax done in base-2 domain)
#define QSCALE 0.1803368801111204f

// ---------------- scratch (device globals; no allocation allowed) ----------
__device__ __align__(16) float g_ctx[ROWS * DIM];

__device__ __align__(16) __nv_bfloat16 g_qhi[ROWS * DIM];
__device__ __align__(16) __nv_bfloat16 g_qlo[ROWS * DIM];
__device__ __align__(16) __nv_bfloat16 g_khi[ROWS * DIM];
__device__ __align__(16) __nv_bfloat16 g_klo[ROWS * DIM];
__device__ __align__(16) __half        g_vh [ROWS * DIM];

// packed split-bf16 GEMM operands
__device__ __align__(16) __nv_bfloat16 g_apack[ROWS * KP];
__device__ __align__(16) __nv_bfloat16 g_bpack[4][DIM * KP];

// ===========================================================================
// PTX helpers (legacy tensor-core path: valid at plain compute_103)
// ===========================================================================
__device__ __forceinline__ uint32_t smem_u32(const void* p) {
    uint32_t a;
    asm("{ .reg .u64 t; cvta.to.shared.u64 t, %1; cvt.u32.u64 %0, t; }"
        : "=r"(a) : "l"(p));
    return a;
}

#define CP_ASYNC16(dst, src) \
    asm volatile("cp.async.cg.shared.global [%0], [%1], 16;" \
                 :: "r"(dst), "l"(src) : "memory")
#define CP_COMMIT() asm volatile("cp.async.commit_group;" ::: "memory")
#define CP_WAIT2()  asm volatile("cp.async.wait_group 2;"  ::: "memory")
#define CP_WAIT1()  asm volatile("cp.async.wait_group 1;"  ::: "memory")

#define LDSM_X4(r, addr) \
    asm volatile("ldmatrix.sync.aligned.m8n8.x4.shared.b16 {%0,%1,%2,%3}, [%4];" \
        : "=r"((r)[0]), "=r"((r)[1]), "=r"((r)[2]), "=r"((r)[3]) : "r"(addr))

#define LDSM_X4_T(r, addr) \
    asm volatile("ldmatrix.sync.aligned.m8n8.x4.trans.shared.b16 {%0,%1,%2,%3}, [%4];" \
        : "=r"((r)[0]), "=r"((r)[1]), "=r"((r)[2]), "=r"((r)[3]) : "r"(addr))

#define MMA16816(d, a, b0, b1) \
    asm volatile("mma.sync.aligned.m16n8k16.row.col.f32.bf16.bf16.f32 " \
        "{%0,%1,%2,%3}, {%4,%5,%6,%7}, {%8,%9}, {%0,%1,%2,%3};" \
        : "+f"((d)[0]), "+f"((d)[1]), "+f"((d)[2]), "+f"((d)[3]) \
        : "r"((a)[0]), "r"((a)[1]), "r"((a)[2]), "r"((a)[3]), "r"(b0), "r"(b1))

#define MMA16816H(d, a, b0, b1) \
    asm volatile("mma.sync.aligned.m16n8k16.row.col.f32.f16.f16.f32 " \
        "{%0,%1,%2,%3}, {%4,%5,%6,%7}, {%8,%9}, {%0,%1,%2,%3};" \
        : "+f"((d)[0]), "+f"((d)[1]), "+f"((d)[2]), "+f"((d)[3]) \
        : "r"((a)[0]), "r"((a)[1]), "r"((a)[2]), "r"((a)[3]), "r"(b0), "r"(b1))

#define EX2F(d, x) asm("ex2.approx.ftz.f32 %0, %1;" : "=f"(d) : "f"(x))
// pack {hi,lo} f32 -> f16x2 (first source -> upper half)
#define PACK_F16X2(d, hi, lo) \
    asm("cvt.rn.f16x2.f32 %0, %1, %2;" : "=r"(d) : "f"(hi), "f"(lo))

// ===========================================================================
// conversion kernels
// ===========================================================================
// A (fp32 [4096,1024]) -> A' bf16 [4096, 3072] = [hi | hi | lo]
__global__ __launch_bounds__(256) void conv_a(
    const float* __restrict__ A, __nv_bfloat16* __restrict__ P)
{
    const int row = blockIdx.x;
    const int c4  = threadIdx.x * 4;
    float4 v = *(const float4*)(A + (size_t)row * DIM + c4);
    float xs[4] = {v.x, v.y, v.z, v.w};
    __align__(8) __nv_bfloat16 h[4], L[4];
    #pragma unroll
    for (int j = 0; j < 4; j++) {
        __nv_bfloat16 hh = __float2bfloat16(xs[j]);
        h[j] = hh;
        L[j] = __float2bfloat16(xs[j] - __bfloat162float(hh));
    }
    __nv_bfloat16* rp = P + (size_t)row * KP;
    *(uint2*)(rp + c4)            = *(const uint2*)h;
    *(uint2*)(rp + DIM + c4)      = *(const uint2*)h;
    *(uint2*)(rp + 2 * DIM + c4)  = *(const uint2*)L;
}

// W (fp32 [K=1024, N=1024]) -> B' bf16 [N=1024, K'=3072] = [hi ; lo ; hi]
__global__ __launch_bounds__(256) void conv_w(
    const float* __restrict__ W, __nv_bfloat16* __restrict__ P)
{
    __shared__ float ws[32][33];
    const int k0 = blockIdx.x * 32;
    const int n0 = blockIdx.y * 32;
    const int t  = threadIdx.x;

    {
        const int kr = t >> 3;
        const int c4 = (t & 7) * 4;
        float4 v = *(const float4*)(W + (size_t)(k0 + kr) * DIM + n0 + c4);
        ws[kr][c4 + 0] = v.x; ws[kr][c4 + 1] = v.y;
        ws[kr][c4 + 2] = v.z; ws[kr][c4 + 3] = v.w;
    }
    __syncthreads();

    const int nr = t >> 3;
    const int k4 = (t & 7) * 4;
    __align__(8) __nv_bfloat16 h[4], L[4];
    #pragma unroll
    for (int j = 0; j < 4; j++) {
        const float x = ws[k4 + j][nr];
        __nv_bfloat16 hh = __float2bfloat16(x);
        h[j] = hh;
        L[j] = __float2bfloat16(x - __bfloat162float(hh));
    }
    __nv_bfloat16* rp = P + (size_t)(n0 + nr) * KP;
    *(uint2*)(rp + k0 + k4)            = *(const uint2*)h;
    *(uint2*)(rp + DIM + k0 + k4)      = *(const uint2*)L;
    *(uint2*)(rp + 2 * DIM + k0 + k4)  = *(const uint2*)h;
}

// ===========================================================================
// HMMA GEMM: C = A'[4096,K'] @ B'^T[N,K'] + bias, with epilogue modes:
//   0: fp32 C     1: Q -> (hi,lo) bf16, scaled by QSCALE
//   2: K -> (hi,lo) bf16            3: V -> f16
// ===========================================================================
#define NCHUNK (KP / 32)       // 96
#define SROW 80
#define TILE_SB (128 * SROW)
#define STAGE_SB (2 * TILE_SB)
#define GSTAGES 4

__global__ __launch_bounds__(256) void gemm_mma(
    const __nv_bfloat16* __restrict__ Ap, const __nv_bfloat16* __restrict__ Bp,
    const float* __restrict__ bias, float* __restrict__ C,
    __nv_bfloat16* __restrict__ Hi, __nv_bfloat16* __restrict__ Lo,
    __half* __restrict__ Vo, int mode)
{
    extern __shared__ __align__(128) char smem[];
    const uint32_t sb = smem_u32(smem);

    const int tid  = threadIdx.x;
    const int lane = tid & 31;
    const int wid  = tid >> 5;
    const int wm   = (wid >> 1) * 32;
    const int wn   = (wid & 1) * 64;
    const int nt   = blockIdx.x;
    const int mt   = blockIdx.y;

    const char* ag = (const char*)(Ap + (size_t)(mt * 128) * KP);
    const char* bg = (const char*)(Bp + (size_t)(nt * 128) * KP);

    auto issue = [&](int kc, int slot) {
        const uint32_t st = sb + slot * STAGE_SB;
        #pragma unroll
        for (int u = 0; u < 4; u++) {
            const int id = tid + u * 256;
            const int isB = id >> 9;
            const int r  = (id >> 2) & 127;
            const int c  = id & 3;
            const uint32_t dst = st + isB * TILE_SB + r * SROW + c * 16;
            const char* src = (isB ? bg : ag) + (size_t)r * (KP * 2) + kc * 64 + c * 16;
            CP_ASYNC16(dst, src);
        }
        CP_COMMIT();
    };

    float acc[2][8][4];
    #pragma unroll
    for (int mi = 0; mi < 2; mi++)
        #pragma unroll
        for (int nj = 0; nj < 8; nj++)
            #pragma unroll
            for (int r = 0; r < 4; r++) acc[mi][nj][r] = 0.f;

    const uint32_t a_row = wm + (lane & 15);
    const uint32_t a_cc  = (lane >> 4) * 16;
    const uint32_t b_row = wn + ((lane >> 4) << 3) + (lane & 7);
    const uint32_t b_cc  = ((lane >> 3) & 1) * 16;

    issue(0, 0); issue(1, 1); issue(2, 2);

    for (int kc = 0; kc < NCHUNK; kc++) {
        const int slot = kc & 3;
        CP_WAIT2();
        __syncthreads();
        if (kc + 3 < NCHUNK) issue(kc + 3, (kc + 3) & 3);
        else CP_COMMIT();

        const uint32_t As = sb + slot * STAGE_SB;
        const uint32_t Bs = As + TILE_SB;

        #pragma unroll
        for (int ki = 0; ki < 2; ki++) {
            uint32_t a[2][4], b[4][4];
            #pragma unroll
            for (int mi = 0; mi < 2; mi++)
                LDSM_X4(a[mi], As + (a_row + mi * 16) * SROW + ki * 32 + a_cc);
            #pragma unroll
            for (int ni = 0; ni < 4; ni++)
                LDSM_X4(b[ni], Bs + (b_row + ni * 16) * SROW + ki * 32 + b_cc);
            #pragma unroll
            for (int mi = 0; mi < 2; mi++)
                #pragma unroll
                for (int nj = 0; nj < 8; nj++)
                    MMA16816(acc[mi][nj], a[mi],
                             b[nj >> 1][(nj & 1) * 2], b[nj >> 1][(nj & 1) * 2 + 1]);
        }
    }

    const int g   = lane >> 2;
    const int tig = lane & 3;
    #pragma unroll
    for (int nj = 0; nj < 8; nj++) {
        const int col = nt * 128 + wn + nj * 8 + tig * 2;
        const float2 bv = *(const float2*)(bias + col);
        #pragma unroll
        for (int mi = 0; mi < 2; mi++) {
            const int m0 = mt * 128 + wm + mi * 16 + g;
            float2 d0 = {acc[mi][nj][0] + bv.x, acc[mi][nj][1] + bv.y};
            float2 d1 = {acc[mi][nj][2] + bv.x, acc[mi][nj][3] + bv.y};
            const size_t i0 = (size_t)m0 * DIM + col;
            const size_t i1 = (size_t)(m0 + 8) * DIM + col;
            if (mode == 0) {
                *(float2*)(C + i0) = d0;
                *(float2*)(C + i1) = d1;
            } else if (mode == 3) {
                *(__half2*)(Vo + i0) = __floats2half2_rn(d0.x, d0.y);
                *(__half2*)(Vo + i1) = __floats2half2_rn(d1.x, d1.y);
            } else {
                if (mode == 1) {
                    d0.x *= QSCALE; d0.y *= QSCALE;
                    d1.x *= QSCALE; d1.y *= QSCALE;
                }
                __nv_bfloat16 h0x = __float2bfloat16(d0.x), h0y = __float2bfloat16(d0.y);
                __nv_bfloat16 h1x = __float2bfloat16(d1.x), h1y = __float2bfloat16(d1.y);
                *(__nv_bfloat162*)(Hi + i0) = __halves2bfloat162(h0x, h0y);
                *(__nv_bfloat162*)(Hi + i1) = __halves2bfloat162(h1x, h1y);
                *(__nv_bfloat162*)(Lo + i0) = __halves2bfloat162(
                    __float2bfloat16(d0.x - __bfloat162float(h0x)),
                    __float2bfloat16(d0.y - __bfloat162float(h0y)));
                *(__nv_bfloat162*)(Lo + i1) = __halves2bfloat162(
                    __float2bfloat16(d1.x - __bfloat162float(h1x)),
                    __float2bfloat16(d1.y - __bfloat162float(h1y)));
            }
        }
    }
}

// ===========================================================================
// HMMA flash attention.
// CTA: (qt 64 rows, head, batch); 4 warps, warp = 16 q rows.
// S = Qhi·Khi + Qhi·Klo + Qlo·Khi (bf16 mma, fp32 acc); base-2 softmax
// (log2e folded into Q); P in f16; O += P·V (f16 mma); row-sums l via
// ones-column MMA. 2-stage cp.async pipeline for K/V tiles.
// ===========================================================================
#define ASROW 144                 // bytes per 64-col bf16/f16 row (128 + 16 pad)
#define SMTILE (64 * ASROW)       // 9216
#define SMS0   (2 * SMTILE)       // Q hi/lo tiles first
#define SMSTAGE (3 * SMTILE)      // khi, klo, v
#define ATTN_SMEM (SMS0 + 2 * SMSTAGE)   // 73728
#define ONE2 0x3C003C00u

__global__ __launch_bounds__(128) void attn_mma(
    const __nv_bfloat16* __restrict__ Qhi, const __nv_bfloat16* __restrict__ Qlo,
    const __nv_bfloat16* __restrict__ Khi, const __nv_bfloat16* __restrict__ Klo,
    const __half* __restrict__ Vh, float* __restrict__ Octx)
{
    extern __shared__ __align__(128) char smem[];
    const uint32_t sb = smem_u32(smem);
    const int tid = threadIdx.x, lane = tid & 31, w = tid >> 5;
    const int qt = blockIdx.x, h = blockIdx.y, b = blockIdx.z;
    const size_t hbase = (size_t)b * SEQ * DIM + (size_t)h * HD;

    // ---- Q tiles (hi+lo) + stage0 in group 0; stage1 in group 1 ----
    #pragma unroll
    for (int u = 0; u < 8; u++) {
        const int id = tid + u * 128;
        const int t8 = id >> 9;
        const int r  = (id >> 3) & 63;
        const int c  = id & 7;
        const uint32_t dst = sb + t8 * SMTILE + r * ASROW + c * 16;
        const __nv_bfloat16* src =
            (t8 ? Qlo : Qhi) + hbase + (size_t)(qt * 64 + r) * DIM + c * 8;
        CP_ASYNC16(dst, src);
    }
    auto issue_kv = [&](int st, int buf) {
        #pragma unroll
        for (int u = 0; u < 12; u++) {
            const int id = tid + u * 128;
            const int t3 = id >> 9;       // 0 khi, 1 klo, 2 v
            const int r  = (id >> 3) & 63;
            const int c  = id & 7;
            const uint32_t dst = sb + SMS0 + buf * SMSTAGE + t3 * SMTILE
                               + r * ASROW + c * 16;
            const size_t off = hbase + (size_t)(st * 64 + r) * DIM + c * 8;
            const void* src = (t3 == 0) ? (const void*)(Khi + off)
                            : (t3 == 1) ? (const void*)(Klo + off)
                                        : (const void*)(Vh + off);
            CP_ASYNC16(dst, src);
        }
    };
    issue_kv(0, 0); CP_COMMIT();
    issue_kv(1, 1); CP_COMMIT();
    CP_WAIT1();
    __syncthreads();

    // ---- hoisted Q fragments ----
    const uint32_t a_row = w * 16 + (lane & 15);
    const uint32_t a_cc  = (lane >> 4) * 16;
    uint32_t qh[4][4], ql[4][4];
    #pragma unroll
    for (int kc = 0; kc < 4; kc++) {
        LDSM_X4(qh[kc], sb + a_row * ASROW + kc * 32 + a_cc);
        LDSM_X4(ql[kc], sb + SMTILE + a_row * ASROW + kc * 32 + a_cc);
    }

    const uint32_t b_row = ((lane >> 4) << 3) + (lane & 7);
    const uint32_t b_cc  = ((lane >> 3) & 1) * 16;
    const uint32_t v_row = (((lane >> 3) & 1) << 3) + (lane & 7);
    const uint32_t v_cc  = (lane >> 4) * 16;

    float m0 = -1e30f, m1 = -1e30f;
    float Of[8][4], Lf[4] = {0.f, 0.f, 0.f, 0.f};
    #pragma unroll
    for (int nt = 0; nt < 8; nt++)
        #pragma unroll
        for (int r = 0; r < 4; r++) Of[nt][r] = 0.f;

    for (int st = 0; st < SEQ / 64; st++) {
        const uint32_t kb = sb + SMS0 + (st & 1) * SMSTAGE;

        // ---- S = scaled Q K^T (split-bf16, 3 products) ----
        float S[8][4];
        #pragma unroll
        for (int nt = 0; nt < 8; nt++)
            #pragma unroll
            for (int r = 0; r < 4; r++) S[nt][r] = 0.f;

        #pragma unroll
        for (int kc = 0; kc < 4; kc++) {
            #pragma unroll
            for (int ng = 0; ng < 4; ng++) {
                uint32_t bh[4], bl[4];
                LDSM_X4(bh, kb + (ng * 16 + b_row) * ASROW + kc * 32 + b_cc);
                LDSM_X4(bl, kb + SMTILE + (ng * 16 + b_row) * ASROW + kc * 32 + b_cc);
                MMA16816(S[2 * ng],     qh[kc], bh[0], bh[1]);
                MMA16816(S[2 * ng],     qh[kc], bl[0], bl[1]);
                MMA16816(S[2 * ng],     ql[kc], bh[0], bh[1]);
                MMA16816(S[2 * ng + 1], qh[kc], bh[2], bh[3]);
                MMA16816(S[2 * ng + 1], qh[kc], bl[2], bl[3]);
                MMA16816(S[2 * ng + 1], ql[kc], bh[2], bh[3]);
            }
        }

        // ---- online softmax (base 2) ----
        float mloc0 = -1e30f, mloc1 = -1e30f;
        #pragma unroll
        for (int nt = 0; nt < 8; nt++) {
            mloc0 = fmaxf(mloc0, fmaxf(S[nt][0], S[nt][1]));
            mloc1 = fmaxf(mloc1, fmaxf(S[nt][2], S[nt][3]));
        }
        mloc0 = fmaxf(mloc0, __shfl_xor_sync(0xffffffffu, mloc0, 1));
        mloc0 = fmaxf(mloc0, __shfl_xor_sync(0xffffffffu, mloc0, 2));
        mloc1 = fmaxf(mloc1, __shfl_xor_sync(0xffffffffu, mloc1, 1));
        mloc1 = fmaxf(mloc1, __shfl_xor_sync(0xffffffffu, mloc1, 2));
        const float mn0 = fmaxf(m0, mloc0), mn1 = fmaxf(m1, mloc1);
        float c0, c1;
        EX2F(c0, m0 - mn0); EX2F(c1, m1 - mn1);
        m0 = mn0; m1 = mn1;
        #pragma unroll
        for (int nt = 0; nt < 8; nt++) {
            Of[nt][0] *= c0; Of[nt][1] *= c0;
            Of[nt][2] *= c1; Of[nt][3] *= c1;
        }
        Lf[0] *= c0; Lf[1] *= c0; Lf[2] *= c1; Lf[3] *= c1;

        uint32_t pa[4][4];
        #pragma unroll
        for (int nt = 0; nt < 8; nt++) {
            float p0, p1, p2, p3;
            EX2F(p0, S[nt][0] - mn0); EX2F(p1, S[nt][1] - mn0);
            EX2F(p2, S[nt][2] - mn1); EX2F(p3, S[nt][3] - mn1);
            uint32_t g0, g8;
            PACK_F16X2(g0, p1, p0);
            PACK_F16X2(g8, p3, p2);
            pa[nt >> 1][(nt & 1) * 2 + 0] = g0;
            pa[nt >> 1][(nt & 1) * 2 + 1] = g8;
        }

        // ---- O += P V ; l += P·1 ----
        #pragma unroll
        for (int kc = 0; kc < 4; kc++) {
            MMA16816H(Lf, pa[kc], ONE2, ONE2);
            #pragma unroll
            for (int hg = 0; hg < 4; hg++) {
                uint32_t bv[4];
                LDSM_X4_T(bv, kb + 2 * SMTILE + (kc * 16 + v_row) * ASROW
                              + hg * 32 + v_cc);
                MMA16816H(Of[2 * hg],     pa[kc], bv[0], bv[1]);
                MMA16816H(Of[2 * hg + 1], pa[kc], bv[2], bv[3]);
            }
        }

        __syncthreads();
        if (st + 2 < SEQ / 64) issue_kv(st + 2, st & 1);
        CP_COMMIT();
        CP_WAIT1();
        __syncthreads();
    }

    // ---- finalize: divide by l, write ctx fp32 ----
    const float i0 = 1.f / Lf[0], i1 = 1.f / Lf[2];
    const int g = lane >> 2, tg = lane & 3;
    const size_t r0 = (size_t)b * SEQ + (size_t)qt * 64 + w * 16 + g;
    #pragma unroll
    for (int nt = 0; nt < 8; nt++) {
        const int col = h * 64 + nt * 8 + tg * 2;
        float2 d0 = {Of[nt][0] * i0, Of[nt][1] * i0};
        float2 d1 = {Of[nt][2] * i1, Of[nt][3] * i1};
        *(float2*)(Octx + r0 * DIM + col)       = d0;
        *(float2*)(Octx + (r0 + 8) * DIM + col) = d1;
    }
}

// ===========================================================================
// launch
// ===========================================================================
extern "C" void kernel_launch(void* const* d_in, const int* in_sizes, int n_in,
                              void* d_out, int out_size)
{
    const float* x  = (const float*)d_in[0];
    const float* Wq = (const float*)d_in[1];
    const float* bq = (const float*)d_in[2];
    const float* Wk = (const float*)d_in[3];
    const float* bk = (const float*)d_in[4];
    const float* Wv = (const float*)d_in[5];
    const float* bv = (const float*)d_in[6];
    const float* Wo = (const float*)d_in[7];
    const float* bo = (const float*)d_in[8];
    float* out = (float*)d_out;

    float* cp;
    cudaGetSymbolAddress((void**)&cp, g_ctx);
    __nv_bfloat16 *ap, *bp, *qhi, *qlo, *khi, *klo;
    __half* vh;
    cudaGetSymbolAddress((void**)&ap,  g_apack);
    cudaGetSymbolAddress((void**)&bp,  g_bpack);
    cudaGetSymbolAddress((void**)&qhi, g_qhi);
    cudaGetSymbolAddress((void**)&qlo, g_qlo);
    cudaGetSymbolAddress((void**)&khi, g_khi);
    cudaGetSymbolAddress((void**)&klo, g_klo);
    cudaGetSymbolAddress((void**)&vh,  g_vh);

    const int gsmem = GSTAGES * STAGE_SB;   // 81920
    cudaFuncSetAttribute(gemm_mma, cudaFuncAttributeMaxDynamicSharedMemorySize, gsmem);
    cudaFuncSetAttribute(attn_mma, cudaFuncAttributeMaxDynamicSharedMemorySize,
                         ATTN_SMEM);

    const dim3 gconv_w(32, 32);
    const dim3 ggemm(8, 32);
    const size_t bstride = (size_t)DIM * KP;

    conv_w<<<gconv_w, 256>>>(Wq, bp + 0 * bstride);
    conv_w<<<gconv_w, 256>>>(Wk, bp + 1 * bstride);
    conv_w<<<gconv_w, 256>>>(Wv, bp + 2 * bstride);
    conv_w<<<gconv_w, 256>>>(Wo, bp + 3 * bstride);

    conv_a<<<ROWS, 256>>>(x, ap);

    // projections -> split bf16 Q (scaled), split bf16 K, f16 V
    gemm_mma<<<ggemm, 256, gsmem>>>(ap, bp + 0 * bstride, bq,
                                    nullptr, qhi, qlo, nullptr, 1);
    gemm_mma<<<ggemm, 256, gsmem>>>(ap, bp + 1 * bstride, bk,
                                    nullptr, khi, klo, nullptr, 2);
    gemm_mma<<<ggemm, 256, gsmem>>>(ap, bp + 2 * bstride, bv,
                                    nullptr, nullptr, nullptr, vh, 3);

    // HMMA flash attention
    attn_mma<<<dim3(SEQ / 64, NHEADS, BATCH), 128, ATTN_SMEM>>>(
        qhi, qlo, khi, klo, vh, cp);

    // output projection
    conv_a<<<ROWS, 256>>>(cp, ap);
    gemm_mma<<<ggemm, 256, gsmem>>>(ap, bp + 3 * bstride, bo,
                                    out, nullptr, nullptr, nullptr, 0);
}

// round 9
// speedup vs baseline: 8.0026x; 1.6737x over previous
#include <cuda_runtime.h>
#include <cuda_bf16.h>
#include <cuda_fp16.h>
#include <cstdint>

#define DIM 1024
#define NHEADS 16
#define HD 64
#define BATCH 2
#define SEQ 2048
#define ROWS (BATCH*SEQ)   // 4096
#define KP2 2048           // f16 split A: [hi | lo]

// Q pre-scale: 1/sqrt(64) * log2(e)  (softmax done in base-2 domain)
#define QSCALE 0.1803368801111204f

// ---------------- scratch (device globals; no allocation allowed) ----------
__device__ __align__(16) float  g_ctx[ROWS * DIM];
__device__ __align__(16) __half g_qhi[ROWS * DIM];
__device__ __align__(16) __half g_qlo[ROWS * DIM];
__device__ __align__(16) __half g_kh [ROWS * DIM];
__device__ __align__(16) __half g_vh [ROWS * DIM];
__device__ __align__(16) __half g_apack[ROWS * KP2];      // [Ah | Al]
__device__ __align__(16) __half g_bpack[4][DIM * DIM];    // W^T f16, 4 planes

// ===========================================================================
// PTX helpers
// ===========================================================================
__device__ __forceinline__ uint32_t smem_u32(const void* p) {
    uint32_t a;
    asm("{ .reg .u64 t; cvta.to.shared.u64 t, %1; cvt.u32.u64 %0, t; }"
        : "=r"(a) : "l"(p));
    return a;
}

#define CP_ASYNC16(dst, src) \
    asm volatile("cp.async.cg.shared.global [%0], [%1], 16;" \
                 :: "r"(dst), "l"(src) : "memory")
#define CP_COMMIT() asm volatile("cp.async.commit_group;" ::: "memory")
#define CP_WAIT1()  asm volatile("cp.async.wait_group 1;"  ::: "memory")

#define LDSM_X4(r, addr) \
    asm volatile("ldmatrix.sync.aligned.m8n8.x4.shared.b16 {%0,%1,%2,%3}, [%4];" \
        : "=r"((r)[0]), "=r"((r)[1]), "=r"((r)[2]), "=r"((r)[3]) : "r"(addr))

#define LDSM_X4_T(r, addr) \
    asm volatile("ldmatrix.sync.aligned.m8n8.x4.trans.shared.b16 {%0,%1,%2,%3}, [%4];" \
        : "=r"((r)[0]), "=r"((r)[1]), "=r"((r)[2]), "=r"((r)[3]) : "r"(addr))

#define MMA16816H(d, a, b0, b1) \
    asm volatile("mma.sync.aligned.m16n8k16.row.col.f32.f16.f16.f32 " \
        "{%0,%1,%2,%3}, {%4,%5,%6,%7}, {%8,%9}, {%0,%1,%2,%3};" \
        : "+f"((d)[0]), "+f"((d)[1]), "+f"((d)[2]), "+f"((d)[3]) \
        : "r"((a)[0]), "r"((a)[1]), "r"((a)[2]), "r"((a)[3]), "r"(b0), "r"(b1))

#define EX2F(d, x) asm("ex2.approx.ftz.f32 %0, %1;" : "=f"(d) : "f"(x))
#define PACK_F16X2(d, hi, lo) \
    asm("cvt.rn.f16x2.f32 %0, %1, %2;" : "=r"(d) : "f"(hi), "f"(lo))

// ===========================================================================
// conversion kernels
// ===========================================================================
// A (fp32 [4096,1024]) -> A' f16 [4096, 2048] = [hi | lo]
__global__ __launch_bounds__(256) void conv_a(
    const float* __restrict__ A, __half* __restrict__ P)
{
    const int row = blockIdx.x;
    const int c4  = threadIdx.x * 4;
    float4 v = *(const float4*)(A + (size_t)row * DIM + c4);
    float xs[4] = {v.x, v.y, v.z, v.w};
    __align__(8) __half h[4], L[4];
    #pragma unroll
    for (int j = 0; j < 4; j++) {
        __half hh = __float2half(xs[j]);
        h[j] = hh;
        L[j] = __float2half(xs[j] - __half2float(hh));
    }
    __half* rp = P + (size_t)row * KP2;
    *(uint2*)(rp + c4)       = *(const uint2*)h;
    *(uint2*)(rp + DIM + c4) = *(const uint2*)L;
}

// 4 weights fused: W (fp32 [K,N]) -> B f16 [N][K] transposed, plane z
__global__ __launch_bounds__(256) void conv_w(
    const float* __restrict__ W0, const float* __restrict__ W1,
    const float* __restrict__ W2, const float* __restrict__ W3,
    __half* __restrict__ P)
{
    __shared__ float ws[32][33];
    const int k0 = blockIdx.x * 32;
    const int n0 = blockIdx.y * 32;
    const int z  = blockIdx.z;
    const float* W = (z == 0) ? W0 : (z == 1) ? W1 : (z == 2) ? W2 : W3;
    const int t  = threadIdx.x;

    {
        const int kr = t >> 3;
        const int c4 = (t & 7) * 4;
        float4 v = *(const float4*)(W + (size_t)(k0 + kr) * DIM + n0 + c4);
        ws[kr][c4 + 0] = v.x; ws[kr][c4 + 1] = v.y;
        ws[kr][c4 + 2] = v.z; ws[kr][c4 + 3] = v.w;
    }
    __syncthreads();

    const int nr = t >> 3;
    const int k4 = (t & 7) * 4;
    __align__(8) __half h[4];
    #pragma unroll
    for (int j = 0; j < 4; j++)
        h[j] = __float2half(ws[k4 + j][nr]);
    *(uint2*)(P + (size_t)z * DIM * DIM + (size_t)(n0 + nr) * DIM + k0 + k4)
        = *(const uint2*)h;
}

// ===========================================================================
// f16 2-product GEMM: C = A @ W + bias  (A exact via hi+lo, W f16-rounded)
// CTA 128x128, 8 warps (4m x 2n), K=1024 in 32 chunks of 32, 3-stage pipeline.
// Epilogue modes: 0 fp32 out; 1 Q -> f16 (hi,lo) scaled; 2 K f16; 3 V f16.
// ===========================================================================
#define NCHUNK 32
#define SROW 80
#define TILE_SB (128 * SROW)       // 10240
#define STAGE3 (3 * TILE_SB)       // 30720: Ahi, Alo, B
#define GSTAGES 3
#define GEMM_SMEM (GSTAGES * STAGE3)   // 92160

__global__ __launch_bounds__(256) void gemm_mma(
    const __half* __restrict__ Ap, const __half* __restrict__ Bp,
    const float* __restrict__ bs0, const float* __restrict__ bs1,
    const float* __restrict__ bs2, float* __restrict__ C,
    __half* __restrict__ Qh, __half* __restrict__ Ql,
    __half* __restrict__ Kh, __half* __restrict__ Vh, int qkv)
{
    extern __shared__ __align__(128) char smem[];
    const uint32_t sb = smem_u32(smem);

    const int tid  = threadIdx.x;
    const int lane = tid & 31;
    const int wid  = tid >> 5;
    const int wm   = (wid >> 1) * 32;
    const int wn   = (wid & 1) * 64;
    const int nt   = blockIdx.x;
    const int mt   = blockIdx.y;
    const int z    = qkv ? (int)blockIdx.z : 0;
    const int mode = qkv ? z + 1 : 0;
    const float* bias = (mode <= 1) ? bs0 : (mode == 2) ? bs1 : bs2;

    const __half* ag = Ap + (size_t)(mt * 128) * KP2;
    const __half* bg = Bp + (size_t)z * DIM * DIM + (size_t)(nt * 128) * DIM;

    auto issue = [&](int kc, int slot) {
        const uint32_t st = sb + slot * STAGE3;
        #pragma unroll
        for (int u = 0; u < 6; u++) {
            const int id = tid + u * 256;
            const int t3 = id >> 9;            // 0 Ahi, 1 Alo, 2 B
            const int r  = (id >> 2) & 127;
            const int c  = id & 3;
            const uint32_t dst = st + t3 * TILE_SB + r * SROW + c * 16;
            const __half* src = (t3 == 2)
                ? bg + (size_t)r * DIM + kc * 32 + c * 8
                : ag + (size_t)r * KP2 + t3 * DIM + kc * 32 + c * 8;
            CP_ASYNC16(dst, src);
        }
        CP_COMMIT();
    };

    float acc[2][8][4];
    #pragma unroll
    for (int mi = 0; mi < 2; mi++)
        #pragma unroll
        for (int nj = 0; nj < 8; nj++)
            #pragma unroll
            for (int r = 0; r < 4; r++) acc[mi][nj][r] = 0.f;

    const uint32_t a_row = wm + (lane & 15);
    const uint32_t a_cc  = (lane >> 4) * 16;
    const uint32_t b_row = wn + ((lane >> 4) << 3) + (lane & 7);
    const uint32_t b_cc  = ((lane >> 3) & 1) * 16;

    issue(0, 0); issue(1, 1);

    for (int kc = 0; kc < NCHUNK; kc++) {
        const int slot = kc % 3;
        CP_WAIT1();
        __syncthreads();
        if (kc + 2 < NCHUNK) issue(kc + 2, (kc + 2) % 3);
        else CP_COMMIT();

        const uint32_t Ah = sb + slot * STAGE3;
        const uint32_t Al = Ah + TILE_SB;
        const uint32_t Bs = Ah + 2 * TILE_SB;

        #pragma unroll
        for (int ki = 0; ki < 2; ki++) {
            uint32_t ah[2][4], al[2][4], b[4][4];
            #pragma unroll
            for (int mi = 0; mi < 2; mi++) {
                LDSM_X4(ah[mi], Ah + (a_row + mi * 16) * SROW + ki * 32 + a_cc);
                LDSM_X4(al[mi], Al + (a_row + mi * 16) * SROW + ki * 32 + a_cc);
            }
            #pragma unroll
            for (int ni = 0; ni < 4; ni++)
                LDSM_X4(b[ni], Bs + (b_row + ni * 16) * SROW + ki * 32 + b_cc);
            #pragma unroll
            for (int mi = 0; mi < 2; mi++)
                #pragma unroll
                for (int nj = 0; nj < 8; nj++) {
                    const uint32_t b0 = b[nj >> 1][(nj & 1) * 2];
                    const uint32_t b1 = b[nj >> 1][(nj & 1) * 2 + 1];
                    MMA16816H(acc[mi][nj], ah[mi], b0, b1);
                    MMA16816H(acc[mi][nj], al[mi], b0, b1);
                }
        }
    }

    const int g   = lane >> 2;
    const int tig = lane & 3;
    #pragma unroll
    for (int nj = 0; nj < 8; nj++) {
        const int col = nt * 128 + wn + nj * 8 + tig * 2;
        const float2 bv = *(const float2*)(bias + col);
        #pragma unroll
        for (int mi = 0; mi < 2; mi++) {
            const int m0 = mt * 128 + wm + mi * 16 + g;
            float2 d0 = {acc[mi][nj][0] + bv.x, acc[mi][nj][1] + bv.y};
            float2 d1 = {acc[mi][nj][2] + bv.x, acc[mi][nj][3] + bv.y};
            const size_t i0 = (size_t)m0 * DIM + col;
            const size_t i1 = (size_t)(m0 + 8) * DIM + col;
            if (mode == 0) {
                *(float2*)(C + i0) = d0;
                *(float2*)(C + i1) = d1;
            } else if (mode == 2) {
                *(__half2*)(Kh + i0) = __floats2half2_rn(d0.x, d0.y);
                *(__half2*)(Kh + i1) = __floats2half2_rn(d1.x, d1.y);
            } else if (mode == 3) {
                *(__half2*)(Vh + i0) = __floats2half2_rn(d0.x, d0.y);
                *(__half2*)(Vh + i1) = __floats2half2_rn(d1.x, d1.y);
            } else {
                d0.x *= QSCALE; d0.y *= QSCALE;
                d1.x *= QSCALE; d1.y *= QSCALE;
                __half2 h0 = __floats2half2_rn(d0.x, d0.y);
                __half2 h1 = __floats2half2_rn(d1.x, d1.y);
                *(__half2*)(Qh + i0) = h0;
                *(__half2*)(Qh + i1) = h1;
                *(__half2*)(Ql + i0) = __floats2half2_rn(
                    d0.x - __half2float(__low2half(h0)),
                    d0.y - __half2float(__high2half(h0)));
                *(__half2*)(Ql + i1) = __floats2half2_rn(
                    d1.x - __half2float(__low2half(h1)),
                    d1.y - __half2float(__high2half(h1)));
            }
        }
    }
}

// ===========================================================================
// HMMA flash attention. S = [Qhi|Qlo] . Kh  (2 f16 products); base-2 softmax;
// P f16; O += P V; row-sums via ones-column MMA. 2-stage cp.async pipeline.
// ===========================================================================
#define ASROW 144
#define SMTILE (64 * ASROW)          // 9216
#define SMS0   (2 * SMTILE)          // Q hi/lo
#define SMSTAGE (2 * SMTILE)         // Kh, V
#define ATTN_SMEM (SMS0 + 2 * SMSTAGE)   // 55296
#define ONE2 0x3C003C00u

__global__ __launch_bounds__(128) void attn_mma(
    const __half* __restrict__ Qhi, const __half* __restrict__ Qlo,
    const __half* __restrict__ Khp, const __half* __restrict__ Vhp,
    float* __restrict__ Octx)
{
    extern __shared__ __align__(128) char smem[];
    const uint32_t sb = smem_u32(smem);
    const int tid = threadIdx.x, lane = tid & 31, w = tid >> 5;
    const int qt = blockIdx.x, h = blockIdx.y, b = blockIdx.z;
    const size_t hbase = (size_t)b * SEQ * DIM + (size_t)h * HD;

    // ---- Q hi/lo tiles (group with stage 0) ----
    #pragma unroll
    for (int u = 0; u < 8; u++) {
        const int id = tid + u * 128;
        const int t2 = id >> 9;
        const int r  = (id >> 3) & 63;
        const int c  = id & 7;
        const uint32_t dst = sb + t2 * SMTILE + r * ASROW + c * 16;
        const __half* src =
            (t2 ? Qlo : Qhi) + hbase + (size_t)(qt * 64 + r) * DIM + c * 8;
        CP_ASYNC16(dst, src);
    }
    auto issue_kv = [&](int st, int buf) {
        #pragma unroll
        for (int u = 0; u < 8; u++) {
            const int id = tid + u * 128;
            const int t2 = id >> 9;       // 0 Kh, 1 V
            const int r  = (id >> 3) & 63;
            const int c  = id & 7;
            const uint32_t dst = sb + SMS0 + buf * SMSTAGE + t2 * SMTILE
                               + r * ASROW + c * 16;
            const size_t off = hbase + (size_t)(st * 64 + r) * DIM + c * 8;
            const __half* src = t2 ? (Vhp + off) : (Khp + off);
            CP_ASYNC16(dst, src);
        }
    };
    issue_kv(0, 0); CP_COMMIT();
    issue_kv(1, 1); CP_COMMIT();
    CP_WAIT1();
    __syncthreads();

    // ---- hoisted Q fragments ----
    const uint32_t a_row = w * 16 + (lane & 15);
    const uint32_t a_cc  = (lane >> 4) * 16;
    uint32_t qh[4][4], ql[4][4];
    #pragma unroll
    for (int kc = 0; kc < 4; kc++) {
        LDSM_X4(qh[kc], sb + a_row * ASROW + kc * 32 + a_cc);
        LDSM_X4(ql[kc], sb + SMTILE + a_row * ASROW + kc * 32 + a_cc);
    }

    const uint32_t b_row = ((lane >> 4) << 3) + (lane & 7);
    const uint32_t b_cc  = ((lane >> 3) & 1) * 16;
    const uint32_t v_row = (((lane >> 3) & 1) << 3) + (lane & 7);
    const uint32_t v_cc  = (lane >> 4) * 16;

    float m0 = -1e30f, m1 = -1e30f;
    float Of[8][4], Lf[4] = {0.f, 0.f, 0.f, 0.f};
    #pragma unroll
    for (int nt = 0; nt < 8; nt++)
        #pragma unroll
        for (int r = 0; r < 4; r++) Of[nt][r] = 0.f;

    for (int st = 0; st < SEQ / 64; st++) {
        const uint32_t kb = sb + SMS0 + (st & 1) * SMSTAGE;

        // ---- S = Q K^T (2 f16 products) ----
        float S[8][4];
        #pragma unroll
        for (int nt = 0; nt < 8; nt++)
            #pragma unroll
            for (int r = 0; r < 4; r++) S[nt][r] = 0.f;

        #pragma unroll
        for (int kc = 0; kc < 4; kc++) {
            #pragma unroll
            for (int ng = 0; ng < 4; ng++) {
                uint32_t bh[4];
                LDSM_X4(bh, kb + (ng * 16 + b_row) * ASROW + kc * 32 + b_cc);
                MMA16816H(S[2 * ng],     qh[kc], bh[0], bh[1]);
                MMA16816H(S[2 * ng],     ql[kc], bh[0], bh[1]);
                MMA16816H(S[2 * ng + 1], qh[kc], bh[2], bh[3]);
                MMA16816H(S[2 * ng + 1], ql[kc], bh[2], bh[3]);
            }
        }

        // ---- online softmax (base 2) ----
        float mloc0 = -1e30f, mloc1 = -1e30f;
        #pragma unroll
        for (int nt = 0; nt < 8; nt++) {
            mloc0 = fmaxf(mloc0, fmaxf(S[nt][0], S[nt][1]));
            mloc1 = fmaxf(mloc1, fmaxf(S[nt][2], S[nt][3]));
        }
        mloc0 = fmaxf(mloc0, __shfl_xor_sync(0xffffffffu, mloc0, 1));
        mloc0 = fmaxf(mloc0, __shfl_xor_sync(0xffffffffu, mloc0, 2));
        mloc1 = fmaxf(mloc1, __shfl_xor_sync(0xffffffffu, mloc1, 1));
        mloc1 = fmaxf(mloc1, __shfl_xor_sync(0xffffffffu, mloc1, 2));
        const float mn0 = fmaxf(m0, mloc0), mn1 = fmaxf(m1, mloc1);
        float c0, c1;
        EX2F(c0, m0 - mn0); EX2F(c1, m1 - mn1);
        m0 = mn0; m1 = mn1;
        #pragma unroll
        for (int nt = 0; nt < 8; nt++) {
            Of[nt][0] *= c0; Of[nt][1] *= c0;
            Of[nt][2] *= c1; Of[nt][3] *= c1;
        }
        Lf[0] *= c0; Lf[1] *= c0; Lf[2] *= c1; Lf[3] *= c1;

        uint32_t pa[4][4];
        #pragma unroll
        for (int nt = 0; nt < 8; nt++) {
            float p0, p1, p2, p3;
            EX2F(p0, S[nt][0] - mn0); EX2F(p1, S[nt][1] - mn0);
            EX2F(p2, S[nt][2] - mn1); EX2F(p3, S[nt][3] - mn1);
            uint32_t g0, g8;
            PACK_F16X2(g0, p1, p0);
            PACK_F16X2(g8, p3, p2);
            pa[nt >> 1][(nt & 1) * 2 + 0] = g0;
            pa[nt >> 1][(nt & 1) * 2 + 1] = g8;
        }

        // ---- O += P V ; l += P.1 ----
        #pragma unroll
        for (int kc = 0; kc < 4; kc++) {
            MMA16816H(Lf, pa[kc], ONE2, ONE2);
            #pragma unroll
            for (int hg = 0; hg < 4; hg++) {
                uint32_t bv[4];
                LDSM_X4_T(bv, kb + SMTILE + (kc * 16 + v_row) * ASROW
                              + hg * 32 + v_cc);
                MMA16816H(Of[2 * hg],     pa[kc], bv[0], bv[1]);
                MMA16816H(Of[2 * hg + 1], pa[kc], bv[2], bv[3]);
            }
        }

        __syncthreads();
        if (st + 2 < SEQ / 64) issue_kv(st + 2, st & 1);
        CP_COMMIT();
        CP_WAIT1();
        __syncthreads();
    }

    // ---- finalize ----
    const float i0 = 1.f / Lf[0], i1 = 1.f / Lf[2];
    const int g = lane >> 2, tg = lane & 3;
    const size_t r0 = (size_t)b * SEQ + (size_t)qt * 64 + w * 16 + g;
    #pragma unroll
    for (int nt = 0; nt < 8; nt++) {
        const int col = h * 64 + nt * 8 + tg * 2;
        float2 d0 = {Of[nt][0] * i0, Of[nt][1] * i0};
        float2 d1 = {Of[nt][2] * i1, Of[nt][3] * i1};
        *(float2*)(Octx + r0 * DIM + col)       = d0;
        *(float2*)(Octx + (r0 + 8) * DIM + col) = d1;
    }
}

// ===========================================================================
// launch
// ===========================================================================
extern "C" void kernel_launch(void* const* d_in, const int* in_sizes, int n_in,
                              void* d_out, int out_size)
{
    const float* x  = (const float*)d_in[0];
    const float* Wq = (const float*)d_in[1];
    const float* bq = (const float*)d_in[2];
    const float* Wk = (const float*)d_in[3];
    const float* bk = (const float*)d_in[4];
    const float* Wv = (const float*)d_in[5];
    const float* bv = (const float*)d_in[6];
    const float* Wo = (const float*)d_in[7];
    const float* bo = (const float*)d_in[8];
    float* out = (float*)d_out;

    float* cp;
    cudaGetSymbolAddress((void**)&cp, g_ctx);
    __half *ap, *bp, *qhi, *qlo, *kh, *vh;
    cudaGetSymbolAddress((void**)&ap,  g_apack);
    cudaGetSymbolAddress((void**)&bp,  g_bpack);
    cudaGetSymbolAddress((void**)&qhi, g_qhi);
    cudaGetSymbolAddress((void**)&qlo, g_qlo);
    cudaGetSymbolAddress((void**)&kh,  g_kh);
    cudaGetSymbolAddress((void**)&vh,  g_vh);

    cudaFuncSetAttribute(gemm_mma, cudaFuncAttributeMaxDynamicSharedMemorySize,
                         GEMM_SMEM);
    cudaFuncSetAttribute(attn_mma, cudaFuncAttributeMaxDynamicSharedMemorySize,
                         ATTN_SMEM);

    // fused weight conversion (4 planes)
    conv_w<<<dim3(32, 32, 4), 256>>>(Wq, Wk, Wv, Wo, bp);

    // x -> f16 hi/lo
    conv_a<<<ROWS, 256>>>(x, ap);

    // fused Q/K/V projections (grid.z selects weight/bias/epilogue)
    gemm_mma<<<dim3(8, 32, 3), 256, GEMM_SMEM>>>(
        ap, bp, bq, bk, bv, nullptr, qhi, qlo, kh, vh, 1);

    // HMMA flash attention
    attn_mma<<<dim3(SEQ / 64, NHEADS, BATCH), 128, ATTN_SMEM>>>(
        qhi, qlo, kh, vh, cp);

    // output projection
    conv_a<<<ROWS, 256>>>(cp, ap);
    gemm_mma<<<dim3(8, 32, 1), 256, GEMM_SMEM>>>(
        ap, bp + 3 * (size_t)DIM * DIM, bo, bo, bo,
        out, nullptr, nullptr, nullptr, nullptr, 0);
}